// round 1
// baseline (speedup 1.0000x reference)
#include <cuda_runtime.h>
#include <math.h>

#define IMG_H 512
#define IMG_W 512
#define NBATCH 4
#define NPTS 512
#define RMAX_CAP 37

// Per-batch radius r[b] = 2 * max_i min_{j!=i} dist(p_i, p_j), computed on device.
__device__ float g_r[NBATCH];

// ---------------------------------------------------------------------------
// Kernel 1: per-batch max-min nearest-neighbor distance.
// One block per batch, 512 threads, points resident in smem.
// sqrt is monotone => maxmin over squared distances, sqrt once at the end.
// ---------------------------------------------------------------------------
__global__ void compute_r_kernel(const float* __restrict__ cp) {
    __shared__ float2 pts[NPTS];
    __shared__ float red[NPTS];
    const int b = blockIdx.x;
    const int t = threadIdx.x;

    const float2* p = reinterpret_cast<const float2*>(cp + (size_t)b * NPTS * 2);
    pts[t] = p[t];
    __syncthreads();

    const float2 me = pts[t];
    float mind2 = 3.0e38f;
#pragma unroll 8
    for (int j = 0; j < NPTS; ++j) {
        float dx = me.x - pts[j].x;
        float dy = me.y - pts[j].y;
        float d2 = fmaf(dy, dy, dx * dx);
        if (j != t) mind2 = fminf(mind2, d2);
    }
    red[t] = mind2;
    __syncthreads();
    for (int s = NPTS / 2; s > 0; s >>= 1) {
        if (t < s) red[t] = fmaxf(red[t], red[t + s]);
        __syncthreads();
    }
    if (t == 0) g_r[b] = 2.0f * sqrtf(red[0]);
}

// ---------------------------------------------------------------------------
// Kernel 2: zero the output (d_out is poisoned to 0xAA before timing).
// ---------------------------------------------------------------------------
__global__ void zero_kernel(float4* __restrict__ out, int n4) {
    int i = blockIdx.x * blockDim.x + threadIdx.x;
    if (i < n4) out[i] = make_float4(0.f, 0.f, 0.f, 0.f);
}

// ---------------------------------------------------------------------------
// Kernel 3: splat. One block per (batch, point); 256 threads stride over the
// (2*rmax)^2 window cells. rmax derived on the fly from g_r (4 loads).
// Scatter via REDG (atomicAdd with unused return).
// ---------------------------------------------------------------------------
__global__ void __launch_bounds__(256, 8)
splat_kernel(const float* __restrict__ cp,
             const float* __restrict__ alpha,
             float* __restrict__ out) {
    const int pid = blockIdx.x;          // 0 .. NBATCH*NPTS-1
    const int b   = pid >> 9;            // /NPTS
    const int t   = threadIdx.x;

    // r_max = int(min(ceil(max_b r_b), 37.0))  -- faithful to reference
    const float r0 = g_r[0], r1 = g_r[1], r2 = g_r[2], r3 = g_r[3];
    const float rmx_f = fmaxf(fmaxf(r0, r1), fmaxf(r2, r3));
    const int   rmax  = (int)fminf(ceilf(rmx_f), (float)RMAX_CAP);
    const int   W2    = 2 * rmax;
    const int   nw    = W2 * W2;

    const float r     = g_r[b];
    const float inv_r = 1.0f / r;

    const float cx = cp[pid * 2 + 0];
    const float cy = cp[pid * 2 + 1];
    const float ax = alpha[pid * 2 + 0];
    const float ay = alpha[pid * 2 + 1];

    // tile = clip(cpoint, r_max, W - r_max); window base = floor(tile) - r_max
    const float lo = (float)rmax, hi = (float)(IMG_W - rmax);
    const float tx = fminf(fmaxf(cx, lo), hi);
    const float ty = fminf(fmaxf(cy, lo), hi);
    const int bx = (int)floorf(tx) - rmax;
    const int by = (int)floorf(ty) - rmax;

    float* __restrict__ out0 = out + (size_t)b * 2 * IMG_H * IMG_W;
    float* __restrict__ out1 = out0 + IMG_H * IMG_W;

    // Incremental (ix, iy) stepping: avoids per-cell integer div/mod.
    const int step_q = 256 / W2;
    const int step_r = 256 % W2;
    int ix = t % W2;
    int iy = t / W2;

    for (int w = t; w < nw; w += 256) {
        const int px = bx + ix;
        const int py = by + iy;
        const float dx = (float)px - cx;
        const float dy = (float)py - cy;
        const float dist = sqrtf(fmaf(dy, dy, dx * dx)) * inv_r;
        if (dist < 1.0f) {
            const float om  = 1.0f - dist;
            const float om2 = om * om;
            const float wgt = om2 * om2 * (4.0f * dist + 1.0f);
            const int off = py * IMG_W + px;
            atomicAdd(out0 + off, wgt * ax);   // -> REDG (no return)
            atomicAdd(out1 + off, wgt * ay);
        }
        ix += step_r;
        iy += step_q;
        if (ix >= W2) { ix -= W2; iy += 1; }
    }
}

// ---------------------------------------------------------------------------
extern "C" void kernel_launch(void* const* d_in, const int* in_sizes, int n_in,
                              void* d_out, int out_size) {
    const float* cpoint = (const float*)d_in[0];  // [4,512,2]
    const float* alpha  = (const float*)d_in[1];  // [4,512,2]
    float* out = (float*)d_out;                   // [4,2,512,512]

    (void)in_sizes; (void)n_in;

    // Zero output (independent of r computation; same stream serializes anyway)
    const int n4 = out_size / 4;                  // 524288 float4s
    zero_kernel<<<(n4 + 255) / 256, 256>>>((float4*)out, n4);

    // Per-batch radius
    compute_r_kernel<<<NBATCH, NPTS>>>(cpoint);

    // Splat
    splat_kernel<<<NBATCH * NPTS, 256>>>(cpoint, alpha, out);
}

// round 2
// speedup vs baseline: 1.1184x; 1.1184x over previous
#include <cuda_runtime.h>
#include <math.h>

#define IMG   512
#define NB    4
#define NP    512
#define RCAP  37
#define PLANE (IMG * IMG)   // 262144

// Per-batch radius r[b] = 2 * max_i min_{j!=i} dist(p_i, p_j)
__device__ float g_r[NB];

// ---------------------------------------------------------------------------
// Kernel 1 (merged): blocks 0..3 compute per-batch max-min NN distance;
// blocks 4..1027 zero the output (4*2*512*512 floats = 524288 float4s).
// ---------------------------------------------------------------------------
__global__ void __launch_bounds__(512)
init_kernel(const float* __restrict__ cp, float4* __restrict__ out) {
    const int blk = blockIdx.x;
    const int t   = threadIdx.x;

    if (blk >= NB) {
        // zero path: 1024 blocks * 512 threads * 1 float4 = 524288 float4s
        out[(blk - NB) * 512 + t] = make_float4(0.f, 0.f, 0.f, 0.f);
        return;
    }

    // max-min path (one block per batch, 512 threads = 512 points)
    __shared__ float2 pts[NP];
    __shared__ float  red[NP];

    const float2* p = reinterpret_cast<const float2*>(cp + (size_t)blk * NP * 2);
    pts[t] = p[t];
    __syncthreads();

    const float2 me = pts[t];
    float mind2 = 3.0e38f;
#pragma unroll 8
    for (int j = 0; j < NP; ++j) {
        float dx = me.x - pts[j].x;
        float dy = me.y - pts[j].y;
        float d2 = fmaf(dy, dy, dx * dx);
        if (j != t) mind2 = fminf(mind2, d2);
    }
    red[t] = mind2;
    __syncthreads();
    for (int s = NP / 2; s >= 32; s >>= 1) {
        if (t < s) red[t] = fmaxf(red[t], red[t + s]);
        __syncthreads();
    }
    if (t < 32) {
        float v = red[t];
#pragma unroll
        for (int o = 16; o > 0; o >>= 1)
            v = fmaxf(v, __shfl_down_sync(0xffffffffu, v, o));
        if (t == 0) g_r[blk] = 2.0f * sqrtf(v);
    }
}

// ---------------------------------------------------------------------------
// Kernel 2: splat. One block per (batch, point), 256 threads.
// lane = window column (coalesced pixels), warp strides rows by 8.
// Incremental float dx/dy (exact integer fp32 adds), single MUFU.RSQ per cell.
// ---------------------------------------------------------------------------
__global__ void __launch_bounds__(256)
splat_kernel(const float* __restrict__ cp,
             const float* __restrict__ alpha,
             float* __restrict__ out) {
    const int pid  = blockIdx.x;          // 0 .. NB*NP-1
    const int b    = pid >> 9;            // / NP
    const int lane = threadIdx.x & 31;
    const int wid  = threadIdx.x >> 5;    // 0..7

    // r_max = int(min(ceil(max_b r_b), 37.0))
    const float rmx  = fmaxf(fmaxf(g_r[0], g_r[1]), fmaxf(g_r[2], g_r[3]));
    const int   rmax = (int)fminf(ceilf(rmx), (float)RCAP);
    const int   W2   = 2 * rmax;

    const float inv_r = 1.0f / g_r[b];

    const float2 c = reinterpret_cast<const float2*>(cp)[pid];
    const float2 a = reinterpret_cast<const float2*>(alpha)[pid];

    // tile = clip(cpoint, r_max, IMG - r_max); window base = floor(tile) - r_max
    const float lo = (float)rmax, hi = (float)(IMG - rmax);
    const int bx = (int)floorf(fminf(fmaxf(c.x, lo), hi)) - rmax;
    const int by = (int)floorf(fminf(fmaxf(c.y, lo), hi)) - rmax;

    float* __restrict__ o0 = out + (size_t)b * 2 * PLANE;
    float* __restrict__ o1 = o0 + PLANE;

    const float dx0 = (float)(bx + lane) - c.x;   // this lane's first column
    float       dy  = (float)(by + wid) - c.y;    // this warp's first row

    for (int iy = wid; iy < W2; iy += 8, dy += 8.0f) {
        const float dy2 = dy * dy;
        int   off = (by + iy) * IMG + bx + lane;
        float dx  = dx0;
        for (int ix = lane; ix < W2; ix += 32, dx += 32.0f, off += 32) {
            const float d2   = fmaf(dx, dx, dy2);
            const float dist = d2 * rsqrtf(fmaxf(d2, 1e-20f)) * inv_r;
            if (dist < 1.0f) {
                const float om  = 1.0f - dist;
                const float om2 = om * om;
                const float w   = (om2 * om2) * fmaf(4.0f, dist, 1.0f);
                atomicAdd(o0 + off, w * a.x);   // REDG, coalesced across lanes
                atomicAdd(o1 + off, w * a.y);
            }
        }
    }
}

// ---------------------------------------------------------------------------
extern "C" void kernel_launch(void* const* d_in, const int* in_sizes, int n_in,
                              void* d_out, int out_size) {
    const float* cpoint = (const float*)d_in[0];  // [4,512,2]
    const float* alpha  = (const float*)d_in[1];  // [4,512,2]
    float* out = (float*)d_out;                   // [4,2,512,512]
    (void)in_sizes; (void)n_in; (void)out_size;

    // 4 reduction blocks + 1024 zeroing blocks
    init_kernel<<<NB + 1024, 512>>>(cpoint, (float4*)out);

    // one block per (batch, point)
    splat_kernel<<<NB * NP, 256>>>(cpoint, alpha, out);
}